// round 4
// baseline (speedup 1.0000x reference)
#include <cuda_runtime.h>

// ---------------- problem constants ----------------
#define Mdim 512
#define Ndim 1024
#define OUTER 200
#define INNER 20
#define RHO 1.0f
#define XSTEP 1e-3f

// ---------------- kernel config ----------------
#define P 128            // persistent CTAs
#define NR 8             // Ndim / P : x/G rows per CTA (one per warp)
#define MR 4             // Mdim / P : m rows per CTA
#define NTHREADS 256
#define XPT 4            // Ndim / NTHREADS
#define RPT 2            // Mdim / NTHREADS
#define NMAIL 32         // private mailboxes (== warp lanes)

typedef unsigned long long u64;

// ---------------- device scratch ----------------
__device__ float g_G[Ndim * Ndim];               // Gram A^T A
__device__ u64 g_xmail[2][NMAIL][Ndim];          // 512 KB tagged x mailboxes
__device__ u64 g_rmail[2][NMAIL][Mdim];          // 256 KB tagged r/u mailboxes

// ---------------- tagged exchange primitives (R2-proven) ----------------
__device__ __forceinline__ u64 pack_val(float v, int seq) {
    return (u64)__float_as_uint(v) | ((u64)(unsigned)seq << 32);
}
__device__ __forceinline__ void st_tag(u64* p, u64 v) {
    asm volatile("st.relaxed.gpu.global.b64 [%0], %1;" :: "l"(p), "l"(v) : "memory");
}
__device__ __forceinline__ u64 ld_tag(const u64* p) {
    u64 v;
    asm volatile("ld.relaxed.gpu.global.b64 %0, [%1];" : "=l"(v) : "l"(p) : "memory");
    return v;
}

// ---------------- init (graph-replay safe) ----------------
#define NINIT (2 * NMAIL * (Ndim + Mdim))
__global__ void k_init_tags() {
    int t = blockIdx.x * blockDim.x + threadIdx.x;
    if (t < 2 * NMAIL * Ndim) ((u64*)g_xmail)[t] = 0ull;
    else if (t < NINIT) ((u64*)g_rmail)[t - 2 * NMAIL * Ndim] = 0ull;
}

// ---------------- G = A^T A ----------------
__global__ void k_gram(const float* __restrict__ A) {
    int i = blockIdx.x * 16 + threadIdx.x;
    int j = blockIdx.y * 16 + threadIdx.y;
    float a0 = 0.f, a1 = 0.f, a2 = 0.f, a3 = 0.f;
    for (int k = 0; k < Mdim; k += 4) {
        float aj0 = __ldg(&A[(k + 0) * Ndim + j]);
        float aj1 = __ldg(&A[(k + 1) * Ndim + j]);
        float aj2 = __ldg(&A[(k + 2) * Ndim + j]);
        float aj3 = __ldg(&A[(k + 3) * Ndim + j]);
        a0 = fmaf(aj0, __ldg(&A[(k + 0) * Ndim + i]), a0);
        a1 = fmaf(aj1, __ldg(&A[(k + 1) * Ndim + i]), a1);
        a2 = fmaf(aj2, __ldg(&A[(k + 2) * Ndim + i]), a2);
        a3 = fmaf(aj3, __ldg(&A[(k + 3) * Ndim + i]), a3);
    }
    g_G[(size_t)j * Ndim + i] = (a0 + a1) + (a2 + a3);
}

__device__ __forceinline__ float warp_allreduce(float acc) {
#pragma unroll
    for (int off = 16; off; off >>= 1)
        acc += __shfl_xor_sync(0xffffffffu, acc, off);
    return acc;
}

// ---------------- main persistent ADMM kernel ----------------
__global__ void __launch_bounds__(NTHREADS, 1)
k_admm(const float* __restrict__ A, const float* __restrict__ b,
       const float* __restrict__ c, float* __restrict__ out) {
    __shared__ float part[2][NR][NTHREADS];   // 16 KB parity partials
    __shared__ float ATs[NR][Mdim];           // 16 KB A^T rows (A cols j0..j0+7)
    __shared__ float rs[Mdim];                // 2 KB r (u at epilogue)

    const int k    = blockIdx.x;
    const int tid  = threadIdx.x;
    const int w    = tid >> 5;
    const int lane = tid & 31;
    const int j0   = k * NR;
    const int i0   = k * MR;
    const int mb   = k & (NMAIL - 1);

    // ---- register-resident matrix chunks ----
    float4 Gr[NR];
#pragma unroll
    for (int r = 0; r < NR; r++)
        Gr[r] = *reinterpret_cast<const float4*>(g_G + (size_t)(j0 + r) * Ndim + tid * XPT);
    float4 Arw[MR];
#pragma unroll
    for (int r = 0; r < MR; r++)
        Arw[r] = *reinterpret_cast<const float4*>(A + (size_t)(i0 + r) * Ndim + tid * XPT);

    for (int t = tid; t < NR * Mdim; t += NTHREADS) {
        int i = t >> 3, r = t & 7;
        ATs[r][i] = A[(size_t)i * Ndim + j0 + r];
    }

    // ---- replicated per-warp state (identical on all lanes) ----
    float xr[XPT];
#pragma unroll
    for (int e = 0; e < XPT; e++) xr[e] = 0.f;
    float xval = 0.f;
    const float cval = c[j0 + w];
    float hval = 0.f;
    float sv = 0.f, uv = 0.f, bv = 0.f;
    if (w < MR) bv = b[i0 + w];

    // ---- publish r^1 = b (s=u=0); lane l -> mailbox l ----
    if (w < MR) st_tag(&g_rmail[1][lane][i0 + w], pack_val(bv, 1));
    __syncthreads();

    for (int o = 0; o < OUTER; o++) {
        // ---- poll r^{o+1} into smem (2 scalar relaxed loads / thread) ----
        {
            const int want = o + 1;
            const u64* bp = &g_rmail[want & 1][mb][tid * RPT];
            unsigned pend = 3u;
            do {
                if (pend & 1u) {
                    u64 v = ld_tag(bp);
                    if ((unsigned)(v >> 32) == (unsigned)want) {
                        rs[tid * RPT] = __uint_as_float((unsigned)v); pend &= ~1u;
                    }
                }
                if (pend & 2u) {
                    u64 v = ld_tag(bp + 1);
                    if ((unsigned)(v >> 32) == (unsigned)want) {
                        rs[tid * RPT + 1] = __uint_as_float((unsigned)v); pend &= ~2u;
                    }
                }
            } while (pend);
        }
        __syncthreads();

        // ---- h = (A^T r)[j0+w] : row-per-warp ----
        {
            const float4* ap = reinterpret_cast<const float4*>(ATs[w]);
            const float4* rp = reinterpret_cast<const float4*>(rs);
            float a0 = 0.f, a1 = 0.f, a2 = 0.f, a3 = 0.f;
#pragma unroll
            for (int q = 0; q < Mdim / 128; q++) {
                float4 a4 = ap[lane + 32 * q], r4 = rp[lane + 32 * q];
                a0 = fmaf(a4.x, r4.x, a0); a1 = fmaf(a4.y, r4.y, a1);
                a2 = fmaf(a4.z, r4.z, a2); a3 = fmaf(a4.w, r4.w, a3);
            }
            hval = warp_allreduce((a0 + a1) + (a2 + a3));
        }

        // ---- inner projected-GD loop ----
        for (int t = 0; t < INNER; t++) {
            const int seq = o * INNER + t;
            const int pty = t & 1;

            // per-thread partials of (G x)
            float* pp = &part[pty][0][tid];
#pragma unroll
            for (int r = 0; r < NR; r++) {
                float a = Gr[r].x * xr[0];
                a = fmaf(Gr[r].y, xr[1], a);
                a = fmaf(Gr[r].z, xr[2], a);
                a = fmaf(Gr[r].w, xr[3], a);
                pp[r * NTHREADS] = a;
            }
            __syncthreads();

            // warp w reduces row w (result on all lanes), update + publish
            {
                const float* rowp = part[pty][w];
                float s = 0.f;
#pragma unroll
                for (int j = 0; j < NTHREADS / 32; j++) s += rowp[lane + 32 * j];
                s = warp_allreduce(s);
                float grad = cval + RHO * (s - hval);
                xval = fmaxf(xval - XSTEP * grad, 0.f);
                st_tag(&g_xmail[(seq + 1) & 1][lane][j0 + w],
                       pack_val(xval, seq + 1));        // lane l -> mailbox l
            }

            // poll x^{seq+1} from private mailbox (4 scalar relaxed loads)
            {
                const int want = seq + 1;
                const u64* b0 = &g_xmail[want & 1][mb][tid * XPT];
                unsigned pend = 15u;
                do {
#pragma unroll
                    for (int e = 0; e < XPT; e++) {
                        if (pend & (1u << e)) {
                            u64 v = ld_tag(b0 + e);
                            if ((unsigned)(v >> 32) == (unsigned)want) {
                                xr[e] = __uint_as_float((unsigned)v);
                                pend &= ~(1u << e);
                            }
                        }
                    }
                } while (pend);
            }
            __syncthreads();   // conservative: protect part[] reuse
        }

        // ---- Ax partials + s,u update + publish next r (or u) ----
        {
            float* pp = &part[0][0][tid];
#pragma unroll
            for (int r = 0; r < MR; r++) {
                float a = Arw[r].x * xr[0];
                a = fmaf(Arw[r].y, xr[1], a);
                a = fmaf(Arw[r].z, xr[2], a);
                a = fmaf(Arw[r].w, xr[3], a);
                pp[r * NTHREADS] = a;
            }
            __syncthreads();
            if (w < MR) {
                const float* rowp = part[0][w];
                float s2 = 0.f;
#pragma unroll
                for (int j = 0; j < NTHREADS / 32; j++) s2 += rowp[lane + 32 * j];
                s2 = warp_allreduce(s2);
                float ax = s2;
                sv = fmaxf(ax - bv + uv, 0.f);
                uv = uv + (ax - sv - bv);
                float rv = (o == OUTER - 1) ? uv : (sv + bv - uv);
                st_tag(&g_rmail[(o + 2) & 1][lane][i0 + w], pack_val(rv, o + 2));
            }
        }
        __syncthreads();
    }

    // ---------------- epilogue ----------------
    // poll u (tag OUTER+1) into rs
    {
        const int want = OUTER + 1;
        const u64* bp = &g_rmail[want & 1][mb][tid * RPT];
        unsigned pend = 3u;
        do {
            if (pend & 1u) {
                u64 v = ld_tag(bp);
                if ((unsigned)(v >> 32) == (unsigned)want) {
                    rs[tid * RPT] = __uint_as_float((unsigned)v); pend &= ~1u;
                }
            }
            if (pend & 2u) {
                u64 v = ld_tag(bp + 1);
                if ((unsigned)(v >> 32) == (unsigned)want) {
                    rs[tid * RPT + 1] = __uint_as_float((unsigned)v); pend &= ~2u;
                }
            }
        } while (pend);
    }
    __syncthreads();

    // x: thread tid holds x[tid*4..+3]; CTA k emits x[8k..8k+7]
    if ((tid >> 1) == k) {
        int base = (tid & 1) * XPT;
#pragma unroll
        for (int e = 0; e < XPT; e++) out[j0 + base + e] = xr[e];
    }
    if (lane == 0 && w < MR) {
        out[Ndim + i0 + w]            = sv;
        out[Ndim + Mdim + i0 + w]     = uv;
        out[Ndim + 2 * Mdim + i0 + w] = fmaxf(-RHO * uv, 0.f);
    }
    // nu = max(c + rho * A^T u, 0)
    {
        const float4* ap = reinterpret_cast<const float4*>(ATs[w]);
        const float4* up = reinterpret_cast<const float4*>(rs);
        float a0 = 0.f, a1 = 0.f, a2 = 0.f, a3 = 0.f;
#pragma unroll
        for (int q = 0; q < Mdim / 128; q++) {
            float4 a4 = ap[lane + 32 * q], u4 = up[lane + 32 * q];
            a0 = fmaf(a4.x, u4.x, a0); a1 = fmaf(a4.y, u4.y, a1);
            a2 = fmaf(a4.z, u4.z, a2); a3 = fmaf(a4.w, u4.w, a3);
        }
        float s = warp_allreduce((a0 + a1) + (a2 + a3));
        if (lane == 0)
            out[Ndim + 3 * Mdim + j0 + w] = fmaxf(cval + RHO * s, 0.f);
    }
}

// ---------------- launch ----------------
extern "C" void kernel_launch(void* const* d_in, const int* in_sizes, int n_in,
                              void* d_out, int out_size) {
    const float *A = nullptr, *b = nullptr, *c = nullptr;
    for (int i = 0; i < n_in; i++) {
        if (in_sizes[i] == Mdim * Ndim)      A = (const float*)d_in[i];
        else if (in_sizes[i] == Mdim)        b = (const float*)d_in[i];
        else if (in_sizes[i] == Ndim)        c = (const float*)d_in[i];
    }
    (void)out_size;

    k_init_tags<<<(NINIT + 255) / 256, 256>>>();
    dim3 gb(16, 16), gg(Ndim / 16, Ndim / 16);
    k_gram<<<gg, gb>>>(A);
    k_admm<<<P, NTHREADS>>>(A, b, c, (float*)d_out);
}